// round 16
// baseline (speedup 1.0000x reference)
#include <cuda_runtime.h>
#include <cstdint>

// Linear-chain CRF log-partition, B=64, T=4096, S=64.
// Linear-space scan: v' = (v @ expT) * exp(s_t) with per-step power-of-2
// renormalization (exponent-field integer math, exact ksum accumulation).
// One warp per batch; exp(transition) columns in registers as f32x2;
// emissions exp() pipelined off the critical path.

typedef unsigned long long ull;

__device__ __forceinline__ ull fma2(ull a, ull b, ull c) {
    ull d;
    asm("fma.rn.f32x2 %0, %1, %2, %3;" : "=l"(d) : "l"(a), "l"(b), "l"(c));
    return d;
}
__device__ __forceinline__ ull add2(ull a, ull b) {
    ull d;
    asm("add.rn.f32x2 %0, %1, %2;" : "=l"(d) : "l"(a), "l"(b));
    return d;
}
__device__ __forceinline__ void upk2(ull v, float& x, float& y) {
    asm("mov.b64 {%0, %1}, %2;" : "=f"(x), "=f"(y) : "l"(v));
}

static __device__ float g_ET[64 * 64];  // exp(transition)

__global__ void crf_expT_kernel(const float* __restrict__ T) {
    int i = blockIdx.x * blockDim.x + threadIdx.x;
    if (i < 64 * 64) g_ET[i] = expf(T[i]);
}

__global__ __launch_bounds__(32, 1)
void crf_scan_kernel(const float* __restrict__ scores,
                     const float* __restrict__ source,
                     const float* __restrict__ sink,
                     float* __restrict__ out) {
    const int lane = threadIdx.x;
    const int b = blockIdx.x;

    __shared__ float4 pd[32];  // pd[lane] = {vx, vx, vy, vy} (duplicated-packed)

    // ET column pair for states j=2*lane, 2*lane+1: et[i] = {ET[i][2l], ET[i][2l+1]}
    ull et[64];
#pragma unroll
    for (int i = 0; i < 64; ++i)
        et[i] = *reinterpret_cast<const ull*>(&g_ET[i * 64 + 2 * lane]);

    const float* sp = scores + ((long)b * 4096) * 64 + 2 * lane;

    const float2 src = *reinterpret_cast<const float2*>(source + 2 * lane);
    const float2 e0 = *reinterpret_cast<const float2*>(sp);
    float a0x = src.x + e0.x, a0y = src.y + e0.y;
    float m0 = __shfl_sync(0xffffffffu, a0x, 0);
    float vx = __expf(a0x - m0);
    float vy = __expf(a0y - m0);
    int ksum = 0;

    // emission pipeline: eCur = exp(s_1), sPre = s_2
    float2 s1 = *reinterpret_cast<const float2*>(sp + 64);
    float2 eCur = make_float2(__expf(s1.x), __expf(s1.y));
    float2 sPre = *reinterpret_cast<const float2*>(sp + 128);

#pragma unroll 1
    for (int t = 1; t < 4096; ++t) {
        // publish (unscaled) v for the all-to-all matvec
        pd[lane] = make_float4(vx, vx, vy, vy);
        float mval = __shfl_sync(0xffffffffu, vx, 0);  // normalizer (off matvec path)
        __syncwarp();

        const float2 emis = eCur;
        // refill pipeline: load s_{t+2}, exp s_{t+1}
        int tp = t + 2;
        if (tp > 4095) tp = 4095;
        float2 sNew = *reinterpret_cast<const float2*>(sp + (long)tp * 64);
        eCur = make_float2(__expf(sPre.x), __expf(sPre.y));
        sPre = sNew;

        // power-of-2 renormalization from lane-0 exponent (integer ops, exact)
        int k = ((__float_as_int(mval) >> 23) & 0xff) - 127;
        ksum += k;
        float sc = __int_as_float((127 - k) << 23);  // 2^-k

        // matvec: v'[j] = sum_i v[i] * ET[i][j], 4 independent packed chains
        const longlong2* p4 = reinterpret_cast<const longlong2*>(pd);
        ull A0 = 0, A1 = 0, A2 = 0, A3 = 0;
#pragma unroll
        for (int kk = 0; kk < 16; ++kk) {
            longlong2 q = p4[kk];
            longlong2 r = p4[kk + 16];
            A0 = fma2((ull)q.x, et[2 * kk], A0);
            A1 = fma2((ull)q.y, et[2 * kk + 1], A1);
            A2 = fma2((ull)r.x, et[2 * kk + 32], A2);
            A3 = fma2((ull)r.y, et[2 * kk + 33], A3);
        }
        float sx, sy;
        upk2(add2(add2(A0, A1), add2(A2, A3)), sx, sy);

        vx = sx * (emis.x * sc);
        vy = sy * (emis.y * sc);
    }

    // epilogue: out[b] = ksum*ln2 + m0 + log(64) + logsumexp_j(log v_j + sink_j)
    const float2 snk = *reinterpret_cast<const float2*>(sink + 2 * lane);
    float t0 = logf(vx) + snk.x;   // logf(0) = -inf handled by fmax/exp
    float t1 = logf(vy) + snk.y;
    float m = fmaxf(t0, t1);
#pragma unroll
    for (int o = 16; o; o >>= 1)
        m = fmaxf(m, __shfl_xor_sync(0xffffffffu, m, o));
    float su = expf(t0 - m) + expf(t1 - m);
#pragma unroll
    for (int o = 16; o; o >>= 1)
        su += __shfl_xor_sync(0xffffffffu, su, o);

    if (lane == 0) {
        double off = (double)ksum * 0.6931471805599453 +
                     (double)m0 + 4.1588830833596715;  // + log(64) (reference quirk)
        out[b] = (float)(off + (double)(m + logf(su)));
    }
}

extern "C" void kernel_launch(void* const* d_in, const int* in_sizes, int n_in,
                              void* d_out, int out_size) {
    (void)in_sizes; (void)n_in; (void)out_size;
    const float* scores     = (const float*)d_in[0];  // (64, 4096, 64)
    const float* transition = (const float*)d_in[1];  // (64, 64)
    const float* source     = (const float*)d_in[2];  // (64,)
    const float* sink       = (const float*)d_in[3];  // (64,)
    float* out = (float*)d_out;                       // (64,)

    crf_expT_kernel<<<8, 512>>>(transition);
    crf_scan_kernel<<<64, 32>>>(scores, source, sink, out);
}

// round 17
// speedup vs baseline: 1.0051x; 1.0051x over previous
#include <cuda_runtime.h>
#include <cstdint>

// Linear-chain CRF log-partition, B=64, T=4096, S=64.
// Linear-space scan: v' = (v @ expT) * exp(s_t) with per-step power-of-2
// renormalization (exponent-field integer math, exact ksum accumulation).
// One warp per batch; exp(transition) columns in registers as f32x2;
// emissions exp() pipelined off the critical path.

typedef unsigned long long ull;

__device__ __forceinline__ ull fma2(ull a, ull b, ull c) {
    ull d;
    asm("fma.rn.f32x2 %0, %1, %2, %3;" : "=l"(d) : "l"(a), "l"(b), "l"(c));
    return d;
}
__device__ __forceinline__ ull add2(ull a, ull b) {
    ull d;
    asm("add.rn.f32x2 %0, %1, %2;" : "=l"(d) : "l"(a), "l"(b));
    return d;
}
__device__ __forceinline__ void upk2(ull v, float& x, float& y) {
    asm("mov.b64 {%0, %1}, %2;" : "=f"(x), "=f"(y) : "l"(v));
}

static __device__ float g_ET[64 * 64];  // exp(transition)

__global__ void crf_expT_kernel(const float* __restrict__ T) {
    int i = blockIdx.x * blockDim.x + threadIdx.x;
    if (i < 64 * 64) g_ET[i] = expf(T[i]);
}

__global__ __launch_bounds__(32, 1)
void crf_scan_kernel(const float* __restrict__ scores,
                     const float* __restrict__ source,
                     const float* __restrict__ sink,
                     float* __restrict__ out) {
    const int lane = threadIdx.x;
    const int b = blockIdx.x;

    __shared__ float4 pd[32];  // pd[lane] = {vx, vx, vy, vy} (duplicated-packed)

    // ET column pair for states j=2*lane, 2*lane+1: et[i] = {ET[i][2l], ET[i][2l+1]}
    ull et[64];
#pragma unroll
    for (int i = 0; i < 64; ++i)
        et[i] = *reinterpret_cast<const ull*>(&g_ET[i * 64 + 2 * lane]);

    const float* sp = scores + ((long)b * 4096) * 64 + 2 * lane;

    const float2 src = *reinterpret_cast<const float2*>(source + 2 * lane);
    const float2 e0 = *reinterpret_cast<const float2*>(sp);
    float a0x = src.x + e0.x, a0y = src.y + e0.y;
    float m0 = __shfl_sync(0xffffffffu, a0x, 0);
    float vx = __expf(a0x - m0);
    float vy = __expf(a0y - m0);
    int ksum = 0;

    // emission pipeline: eCur = exp(s_1), sPre = s_2
    float2 s1 = *reinterpret_cast<const float2*>(sp + 64);
    float2 eCur = make_float2(__expf(s1.x), __expf(s1.y));
    float2 sPre = *reinterpret_cast<const float2*>(sp + 128);

#pragma unroll 1
    for (int t = 1; t < 4096; ++t) {
        // publish (unscaled) v for the all-to-all matvec
        pd[lane] = make_float4(vx, vx, vy, vy);
        float mval = __shfl_sync(0xffffffffu, vx, 0);  // normalizer (off matvec path)
        __syncwarp();

        const float2 emis = eCur;
        // refill pipeline: load s_{t+2}, exp s_{t+1}
        int tp = t + 2;
        if (tp > 4095) tp = 4095;
        float2 sNew = *reinterpret_cast<const float2*>(sp + (long)tp * 64);
        eCur = make_float2(__expf(sPre.x), __expf(sPre.y));
        sPre = sNew;

        // power-of-2 renormalization from lane-0 exponent (integer ops, exact)
        int k = ((__float_as_int(mval) >> 23) & 0xff) - 127;
        ksum += k;
        float sc = __int_as_float((127 - k) << 23);  // 2^-k

        // matvec: v'[j] = sum_i v[i] * ET[i][j], 4 independent packed chains
        const longlong2* p4 = reinterpret_cast<const longlong2*>(pd);
        ull A0 = 0, A1 = 0, A2 = 0, A3 = 0;
#pragma unroll
        for (int kk = 0; kk < 16; ++kk) {
            longlong2 q = p4[kk];
            longlong2 r = p4[kk + 16];
            A0 = fma2((ull)q.x, et[2 * kk], A0);
            A1 = fma2((ull)q.y, et[2 * kk + 1], A1);
            A2 = fma2((ull)r.x, et[2 * kk + 32], A2);
            A3 = fma2((ull)r.y, et[2 * kk + 33], A3);
        }
        float sx, sy;
        upk2(add2(add2(A0, A1), add2(A2, A3)), sx, sy);

        vx = sx * (emis.x * sc);
        vy = sy * (emis.y * sc);
    }

    // epilogue: out[b] = ksum*ln2 + m0 + log(64) + logsumexp_j(log v_j + sink_j)
    const float2 snk = *reinterpret_cast<const float2*>(sink + 2 * lane);
    float t0 = logf(vx) + snk.x;   // logf(0) = -inf handled by fmax/exp
    float t1 = logf(vy) + snk.y;
    float m = fmaxf(t0, t1);
#pragma unroll
    for (int o = 16; o; o >>= 1)
        m = fmaxf(m, __shfl_xor_sync(0xffffffffu, m, o));
    float su = expf(t0 - m) + expf(t1 - m);
#pragma unroll
    for (int o = 16; o; o >>= 1)
        su += __shfl_xor_sync(0xffffffffu, su, o);

    if (lane == 0) {
        double off = (double)ksum * 0.6931471805599453 +
                     (double)m0 + 4.1588830833596715;  // + log(64) (reference quirk)
        out[b] = (float)(off + (double)(m + logf(su)));
    }
}

extern "C" void kernel_launch(void* const* d_in, const int* in_sizes, int n_in,
                              void* d_out, int out_size) {
    (void)in_sizes; (void)n_in; (void)out_size;
    const float* scores     = (const float*)d_in[0];  // (64, 4096, 64)
    const float* transition = (const float*)d_in[1];  // (64, 64)
    const float* source     = (const float*)d_in[2];  // (64,)
    const float* sink       = (const float*)d_in[3];  // (64,)
    float* out = (float*)d_out;                       // (64,)

    crf_expT_kernel<<<8, 512>>>(transition);
    crf_scan_kernel<<<64, 32>>>(scores, source, sink, out);
}